// round 6
// baseline (speedup 1.0000x reference)
#include <cuda_runtime.h>
#include <cuda_bf16.h>
#include <cstdint>
#include <math.h>

// ---------------------------------------------------------------------------
// SwinBlock on sm_103a — bf16x3 HMMA GEMMs, cp.async 3-stage pipeline.
// B=16, H=W=56, C=192, heads=6 (hd=32), WS=7, SHIFT=3, HIDDEN=1152
// (tcgen05 unavailable: harness compiles PTX at .target sm_103 w/o 'a')
// ---------------------------------------------------------------------------

#define WSZ    7
#define SHIFT  3
#define HEADS  6
#define DIM    192
#define HIDDEN 1152
#define EPS    1e-5f
#define IMG    56
#define NTOK   49
#define MAXM   50176   // 16*56*56

typedef __nv_bfloat16 bf16;

// ------------------------- scratch (static device) -------------------------
__device__ float g_qkv [(size_t)MAXM * 3 * DIM];
__device__ float g_x2  [(size_t)MAXM * DIM];
__device__ bf16  g_h_hi[(size_t)MAXM * DIM];
__device__ bf16  g_h_lo[(size_t)MAXM * DIM];
__device__ bf16  g_at_hi[(size_t)MAXM * DIM];
__device__ bf16  g_at_lo[(size_t)MAXM * DIM];
__device__ bf16  g_hid_hi[(size_t)MAXM * HIDDEN];
__device__ bf16  g_hid_lo[(size_t)MAXM * HIDDEN];
__device__ bf16  g_wq_hi[576 * DIM],      g_wq_lo[576 * DIM];
__device__ bf16  g_wp_hi[DIM * DIM],      g_wp_lo[DIM * DIM];
__device__ bf16  g_w1_hi[HIDDEN * DIM],   g_w1_lo[HIDDEN * DIM];
__device__ bf16  g_w2_hi[DIM * HIDDEN],   g_w2_lo[DIM * HIDDEN];

__device__ __forceinline__ int win_to_orig(int r) {
    int w   = r / NTOK;
    int n   = r - w * NTOK;
    int b   = w >> 6;
    int win = w & 63;
    int hs  = (win >> 3) * WSZ + n / WSZ;
    int ws  = (win & 7)  * WSZ + n % WSZ;
    int h   = hs + SHIFT; if (h >= IMG) h -= IMG;
    int x   = ws + SHIFT; if (x >= IMG) x -= IMG;
    return b * (IMG * IMG) + h * IMG + x;
}

__device__ __forceinline__ void split_bf16(float v, bf16& hi, bf16& lo) {
    hi = __float2bfloat16(v);
    lo = __float2bfloat16(v - __bfloat162float(hi));
}

// ------------------------- weight conversion -------------------------------
__global__ void conv_kernel(const float* __restrict__ w, bf16* __restrict__ hi,
                            bf16* __restrict__ lo, int n) {
    for (int i = blockIdx.x * blockDim.x + threadIdx.x; i < n; i += gridDim.x * blockDim.x) {
        bf16 h, l; split_bf16(w[i], h, l);
        hi[i] = h; lo[i] = l;
    }
}

// ------------------------- LayerNorm ---------------------------------------
__global__ void ln_kernel(const float* __restrict__ in, bf16* __restrict__ ohi,
                          bf16* __restrict__ olo,
                          const float* __restrict__ gam, const float* __restrict__ bet,
                          int M, int remap) {
    int r = blockIdx.x * (blockDim.x >> 5) + (threadIdx.x >> 5);
    if (r >= M) return;
    int lane = threadIdx.x & 31;
    int src  = remap ? win_to_orig(r) : r;
    const float* row = in + (size_t)src * DIM;

    float v[6], s = 0.f;
#pragma unroll
    for (int j = 0; j < 6; j++) { v[j] = row[lane + 32 * j]; s += v[j]; }
#pragma unroll
    for (int o = 16; o; o >>= 1) s += __shfl_xor_sync(0xFFFFFFFFu, s, o);
    float mean = s * (1.f / DIM);
    float vs = 0.f;
#pragma unroll
    for (int j = 0; j < 6; j++) { float d = v[j] - mean; vs += d * d; }
#pragma unroll
    for (int o = 16; o; o >>= 1) vs += __shfl_xor_sync(0xFFFFFFFFu, vs, o);
    float rstd = rsqrtf(vs * (1.f / DIM) + EPS);

    size_t ro = (size_t)r * DIM;
#pragma unroll
    for (int j = 0; j < 6; j++) {
        int c = lane + 32 * j;
        float y = (v[j] - mean) * rstd * gam[c] + bet[c];
        bf16 h, l; split_bf16(y, h, l);
        ohi[ro + c] = h; olo[ro + c] = l;
    }
}

// ------------------------- mma.sync helpers --------------------------------
__device__ __forceinline__ void ldsm4(uint32_t r[4], const bf16* p) {
    uint32_t a = (uint32_t)__cvta_generic_to_shared(p);
    asm volatile("ldmatrix.sync.aligned.m8n8.x4.shared.b16 {%0,%1,%2,%3}, [%4];"
                 : "=r"(r[0]), "=r"(r[1]), "=r"(r[2]), "=r"(r[3]) : "r"(a));
}
__device__ __forceinline__ void mma16816(float c[4], const uint32_t a[4],
                                         uint32_t b0, uint32_t b1) {
    asm volatile(
        "mma.sync.aligned.m16n8k16.row.col.f32.bf16.bf16.f32 "
        "{%0,%1,%2,%3}, {%4,%5,%6,%7}, {%8,%9}, {%0,%1,%2,%3};"
        : "+f"(c[0]), "+f"(c[1]), "+f"(c[2]), "+f"(c[3])
        : "r"(a[0]), "r"(a[1]), "r"(a[2]), "r"(a[3]), "r"(b0), "r"(b1));
}
__device__ __forceinline__ void cp16(bf16* dst, const bf16* src) {
    uint32_t d = (uint32_t)__cvta_generic_to_shared(dst);
    asm volatile("cp.async.cg.shared.global [%0], [%1], 16;" :: "r"(d), "l"(src));
}
__device__ __forceinline__ void cp_commit() {
    asm volatile("cp.async.commit_group;" ::: "memory");
}
template <int N>
__device__ __forceinline__ void cp_wait() {
    asm volatile("cp.async.wait_group %0;" :: "n"(N) : "memory");
}

// ---------------------------------------------------------------------------
// Tensor-core GEMM, 3-stage cp.async pipeline.
// C[M,N] = (Ahi+Alo)[M,K] @ (Whi+Wlo)[N,K]^T + bias  (bf16x3, fp32 accum)
// BM=256, BN=64, BK=32; 256 threads = 8 warps, each warp 32(m) x 64(n).
// MODE 0: fp32 (qkv)   MODE 1: remap+residual (proj)
// MODE 2: GELU->hi/lo  MODE 3: residual (fc2 -> out)
// ---------------------------------------------------------------------------
#define SKP 40                    // bf16 per 32-k smem row (padded)
#define ST_AH 0
#define ST_AL (256 * SKP)         // 10240 bf16
#define ST_WH (512 * SKP)         // 20480
#define ST_WL (512 * SKP + 64 * SKP)
#define STAGE_ELEMS (512 * SKP + 128 * SKP)  // 25600 bf16 = 51200 B
#define GSMEM_BYTES (3 * STAGE_ELEMS * 2)    // 153600 B

template <int MODE>
__global__ void __launch_bounds__(256)
gemm_tc(const bf16* __restrict__ Ahi, const bf16* __restrict__ Alo,
        const bf16* __restrict__ Whi, const bf16* __restrict__ Wlo,
        const float* __restrict__ bias, int N, int K,
        float* __restrict__ Cf, bf16* __restrict__ Chi, bf16* __restrict__ Clo,
        const float* __restrict__ res) {
    extern __shared__ bf16 sm[];
    const int m0 = blockIdx.y * 256, n0 = blockIdx.x * 64;
    const int tid = threadIdx.x, lane = tid & 31, w = tid >> 5;
    const int NC = K / 32;

    auto load_stage = [&](int c) {
        bf16* buf = sm + (c % 3) * STAGE_ELEMS;
        const int k0 = c * 32;
#pragma unroll
        for (int it = 0; it < 4; it++) {           // A: 1024 16B chunks
            int i = tid + it * 256;
            int row = i >> 2, q = i & 3;
            size_t g = (size_t)(m0 + row) * K + k0 + q * 8;
            int so = row * SKP + q * 8;
            cp16(buf + ST_AH + so, Ahi + g);
            cp16(buf + ST_AL + so, Alo + g);
        }
        {                                           // W: 256 16B chunks
            int row = tid >> 2, q = tid & 3;
            size_t g = (size_t)(n0 + row) * K + k0 + q * 8;
            int so = row * SKP + q * 8;
            cp16(buf + ST_WH + so, Whi + g);
            cp16(buf + ST_WL + so, Wlo + g);
        }
        cp_commit();
    };

    float acc[2][8][4] = {};

    load_stage(0);
    load_stage(1);

    for (int c = 0; c < NC; c++) {
        if (c + 1 < NC) cp_wait<1>(); else cp_wait<0>();
        __syncthreads();
        if (c + 2 < NC) load_stage(c + 2);

        bf16* buf = sm + (c % 3) * STAGE_ELEMS;
        const int lrow = lane & 15;
#pragma unroll
        for (int kk = 0; kk < 2; kk++) {
            const int lcol = kk * 16 + (lane >> 4) * 8;
            uint32_t ah[2][4], al[2][4], wh[4][4], wl[4][4];
#pragma unroll
            for (int mi = 0; mi < 2; mi++) {
                const bf16* pa = buf + ST_AH + (w * 32 + mi * 16 + lrow) * SKP + lcol;
                ldsm4(ah[mi], pa);
                ldsm4(al[mi], pa + (ST_AL - ST_AH));
            }
#pragma unroll
            for (int nj = 0; nj < 4; nj++) {
                const bf16* pw = buf + ST_WH + (nj * 16 + lrow) * SKP + lcol;
                ldsm4(wh[nj], pw);
                ldsm4(wl[nj], pw + (ST_WL - ST_WH));
            }
#pragma unroll
            for (int mi = 0; mi < 2; mi++)
#pragma unroll
                for (int nj = 0; nj < 4; nj++)
#pragma unroll
                    for (int j = 0; j < 2; j++) {
                        float* cacc = acc[mi][nj * 2 + j];
                        mma16816(cacc, ah[mi], wh[nj][j], wh[nj][2 + j]);
                        mma16816(cacc, al[mi], wh[nj][j], wh[nj][2 + j]);
                        mma16816(cacc, ah[mi], wl[nj][j], wl[nj][2 + j]);
                    }
        }
        __syncthreads();
    }

    // ---------------- epilogue ----------------
    const int g = lane >> 2, t4 = lane & 3;
#pragma unroll
    for (int mi = 0; mi < 2; mi++) {
#pragma unroll
        for (int half = 0; half < 2; half++) {
            int r = m0 + w * 32 + mi * 16 + g + half * 8;
            int ro = (MODE == 1) ? win_to_orig(r) : r;
#pragma unroll
            for (int nj = 0; nj < 8; nj++) {
                int cc = n0 + nj * 8 + t4 * 2;
                float v0 = acc[mi][nj][half * 2 + 0] + bias[cc];
                float v1 = acc[mi][nj][half * 2 + 1] + bias[cc + 1];
                if (MODE == 0) {
                    *(float2*)&Cf[(size_t)r * N + cc] = make_float2(v0, v1);
                } else if (MODE == 1) {
                    size_t o = (size_t)ro * DIM + cc;
                    Cf[o]     = v0 + res[o];
                    Cf[o + 1] = v1 + res[o + 1];
                } else if (MODE == 2) {
                    v0 = 0.5f * v0 * (1.0f + erff(v0 * 0.70710678118654752f));
                    v1 = 0.5f * v1 * (1.0f + erff(v1 * 0.70710678118654752f));
                    bf16 h0, l0, h1, l1;
                    split_bf16(v0, h0, l0); split_bf16(v1, h1, l1);
                    size_t o = (size_t)r * N + cc;
                    *(__nv_bfloat162*)&Chi[o] = __nv_bfloat162(h0, h1);
                    *(__nv_bfloat162*)&Clo[o] = __nv_bfloat162(l0, l1);
                } else { // MODE 3
                    size_t o = (size_t)r * DIM + cc;
                    Cf[o]     = v0 + res[o];
                    Cf[o + 1] = v1 + res[o + 1];
                }
            }
        }
    }
}

// ---------------------------------------------------------------------------
// Windowed attention (fp32): one block per (window, head). 64 threads.
// ---------------------------------------------------------------------------
__global__ void attn_kernel(const float* __restrict__ qkv,
                            const float* __restrict__ rpb,
                            bf16* __restrict__ ohi, bf16* __restrict__ olo) {
    __shared__ float q[NTOK][33], k[NTOK][33], v[NTOK][33];
    __shared__ float at[NTOK][51];
    __shared__ float bsh[169];

    const int w    = blockIdx.x / HEADS;
    const int head = blockIdx.x % HEADS;
    const int t    = threadIdx.x;

    const float* base = qkv + (size_t)w * NTOK * (3 * DIM) + head * 32;
    for (int idx = t; idx < NTOK * 32 * 3; idx += 64) {
        int part = idx / (NTOK * 32);
        int rem  = idx - part * NTOK * 32;
        int n = rem >> 5, d = rem & 31;
        float val = base[(size_t)n * (3 * DIM) + part * DIM + d];
        if      (part == 0) q[n][d] = val;
        else if (part == 1) k[n][d] = val;
        else                v[n][d] = val;
    }
    for (int idx = t; idx < 169; idx += 64) bsh[idx] = rpb[idx * HEADS + head];
    __syncthreads();

    if (t < NTOK) {
        const float scale = 0.17677669529663687f;
        int pin = t / WSZ, pjn = t % WSZ;
        float mx = -1e30f;
#pragma unroll 7
        for (int m = 0; m < NTOK; m++) {
            float s = 0.f;
#pragma unroll
            for (int d = 0; d < 32; d++) s = fmaf(q[t][d], k[m][d], s);
            int idx = (pin - m / WSZ + 6) * 13 + (pjn - m % WSZ + 6);
            s = s * scale + bsh[idx];
            at[t][m] = s;
            mx = fmaxf(mx, s);
        }
        float sum = 0.f;
#pragma unroll 7
        for (int m = 0; m < NTOK; m++) {
            float e = __expf(at[t][m] - mx);
            at[t][m] = e;
            sum += e;
        }
        float inv = 1.0f / sum;
        size_t orow = (size_t)(w * NTOK + t) * DIM + head * 32;
#pragma unroll
        for (int d = 0; d < 32; d++) {
            float o = 0.f;
#pragma unroll 7
            for (int m = 0; m < NTOK; m++) o = fmaf(at[t][m], v[m][d], o);
            o *= inv;
            bf16 h, l; split_bf16(o, h, l);
            ohi[orow + d] = h; olo[orow + d] = l;
        }
    }
}

// ---------------------------------------------------------------------------
extern "C" void kernel_launch(void* const* d_in, const int* in_sizes, int n_in,
                              void* d_out, int out_size) {
    const float* x = (const float*)d_in[0];
    int base = n_in - 13;
    const float* ln1_g  = (const float*)d_in[base + 0];
    const float* ln1_b  = (const float*)d_in[base + 1];
    const float* qkv_w  = (const float*)d_in[base + 2];
    const float* qkv_b  = (const float*)d_in[base + 3];
    const float* rpb    = (const float*)d_in[base + 4];
    const float* proj_w = (const float*)d_in[base + 5];
    const float* proj_b = (const float*)d_in[base + 6];
    const float* ln2_g  = (const float*)d_in[base + 7];
    const float* ln2_b  = (const float*)d_in[base + 8];
    const float* fc1_w  = (const float*)d_in[base + 9];
    const float* fc1_b  = (const float*)d_in[base + 10];
    const float* fc2_w  = (const float*)d_in[base + 11];
    const float* fc2_b  = (const float*)d_in[base + 12];

    const int Bsz = in_sizes[0] / (IMG * IMG * DIM);
    const int M   = Bsz * IMG * IMG;

    float *qkv, *x2;
    bf16 *h_hi, *h_lo, *at_hi, *at_lo, *hid_hi, *hid_lo;
    bf16 *wq_hi, *wq_lo, *wp_hi, *wp_lo, *w1_hi, *w1_lo, *w2_hi, *w2_lo;
    cudaGetSymbolAddress((void**)&qkv,    g_qkv);
    cudaGetSymbolAddress((void**)&x2,     g_x2);
    cudaGetSymbolAddress((void**)&h_hi,   g_h_hi);
    cudaGetSymbolAddress((void**)&h_lo,   g_h_lo);
    cudaGetSymbolAddress((void**)&at_hi,  g_at_hi);
    cudaGetSymbolAddress((void**)&at_lo,  g_at_lo);
    cudaGetSymbolAddress((void**)&hid_hi, g_hid_hi);
    cudaGetSymbolAddress((void**)&hid_lo, g_hid_lo);
    cudaGetSymbolAddress((void**)&wq_hi,  g_wq_hi);
    cudaGetSymbolAddress((void**)&wq_lo,  g_wq_lo);
    cudaGetSymbolAddress((void**)&wp_hi,  g_wp_hi);
    cudaGetSymbolAddress((void**)&wp_lo,  g_wp_lo);
    cudaGetSymbolAddress((void**)&w1_hi,  g_w1_hi);
    cudaGetSymbolAddress((void**)&w1_lo,  g_w1_lo);
    cudaGetSymbolAddress((void**)&w2_hi,  g_w2_hi);
    cudaGetSymbolAddress((void**)&w2_lo,  g_w2_lo);

    cudaFuncSetAttribute(gemm_tc<0>, cudaFuncAttributeMaxDynamicSharedMemorySize, GSMEM_BYTES);
    cudaFuncSetAttribute(gemm_tc<1>, cudaFuncAttributeMaxDynamicSharedMemorySize, GSMEM_BYTES);
    cudaFuncSetAttribute(gemm_tc<2>, cudaFuncAttributeMaxDynamicSharedMemorySize, GSMEM_BYTES);
    cudaFuncSetAttribute(gemm_tc<3>, cudaFuncAttributeMaxDynamicSharedMemorySize, GSMEM_BYTES);

    const int lnGrid = (M + 7) / 8;
    const int mT = M / 256;   // 196

    conv_kernel<<<216, 256>>>(qkv_w,  wq_hi, wq_lo, 576 * DIM);
    conv_kernel<<<72,  256>>>(proj_w, wp_hi, wp_lo, DIM * DIM);
    conv_kernel<<<432, 256>>>(fc1_w,  w1_hi, w1_lo, HIDDEN * DIM);
    conv_kernel<<<432, 256>>>(fc2_w,  w2_hi, w2_lo, DIM * HIDDEN);

    // 1. LN1 fused shift + window partition
    ln_kernel<<<lnGrid, 256>>>(x, h_hi, h_lo, ln1_g, ln1_b, M, 1);
    // 2. QKV GEMM (fp32 out)
    gemm_tc<0><<<dim3(576 / 64, mT), 256, GSMEM_BYTES>>>(
        h_hi, h_lo, wq_hi, wq_lo, qkv_b, 576, DIM, qkv, nullptr, nullptr, nullptr);
    // 3. attention
    attn_kernel<<<(M / NTOK) * HEADS, 64>>>(qkv, rpb, at_hi, at_lo);
    // 4. proj GEMM + window-reverse + residual
    gemm_tc<1><<<dim3(DIM / 64, mT), 256, GSMEM_BYTES>>>(
        at_hi, at_lo, wp_hi, wp_lo, proj_b, DIM, DIM, x2, nullptr, nullptr, x);
    // 5. LN2
    ln_kernel<<<lnGrid, 256>>>(x2, h_hi, h_lo, ln2_g, ln2_b, M, 0);
    // 6. fc1 GEMM + GELU
    gemm_tc<2><<<dim3(HIDDEN / 64, mT), 256, GSMEM_BYTES>>>(
        h_hi, h_lo, w1_hi, w1_lo, fc1_b, HIDDEN, DIM, nullptr, hid_hi, hid_lo, nullptr);
    // 7. fc2 GEMM + residual -> d_out
    gemm_tc<3><<<dim3(DIM / 64, mT), 256, GSMEM_BYTES>>>(
        hid_hi, hid_lo, w2_hi, w2_lo, fc2_b, DIM, HIDDEN, (float*)d_out, nullptr, nullptr, x2);
}

// round 8
// speedup vs baseline: 1.4147x; 1.4147x over previous
#include <cuda_runtime.h>
#include <cuda_fp16.h>
#include <cstdint>
#include <math.h>

// ---------------------------------------------------------------------------
// SwinBlock on sm_103a — fp16x2 HMMA GEMMs (A fp16, W hi/lo fp16, fp32 accum).
// 3-stage cp.async pipeline, BM=128/BN=64 (2+ CTAs/SM).
// B=16, H=W=56, C=192, heads=6 (hd=32), WS=7, SHIFT=3, HIDDEN=1152
// ---------------------------------------------------------------------------

#define WSZ    7
#define SHIFT  3
#define HEADS  6
#define DIM    192
#define HIDDEN 1152
#define EPS    1e-5f
#define IMG    56
#define NTOK   49
#define MAXM   50176   // 16*56*56

typedef __half f16;

// ------------------------- scratch (static device) -------------------------
__device__ float g_qkv [(size_t)MAXM * 3 * DIM];   // fp32 for attention
__device__ float g_x2  [(size_t)MAXM * DIM];
__device__ f16   g_h   [(size_t)MAXM * DIM];       // LN out (reused LN1/LN2)
__device__ f16   g_at  [(size_t)MAXM * DIM];       // attention out (window layout)
__device__ f16   g_hid [(size_t)MAXM * HIDDEN];    // gelu(fc1)
__device__ f16   g_wq_hi[576 * DIM],    g_wq_lo[576 * DIM];
__device__ f16   g_wp_hi[DIM * DIM],    g_wp_lo[DIM * DIM];
__device__ f16   g_w1_hi[HIDDEN * DIM], g_w1_lo[HIDDEN * DIM];
__device__ f16   g_w2_hi[DIM * HIDDEN], g_w2_lo[DIM * HIDDEN];

__device__ __forceinline__ int win_to_orig(int r) {
    int w   = r / NTOK;
    int n   = r - w * NTOK;
    int b   = w >> 6;
    int win = w & 63;
    int hs  = (win >> 3) * WSZ + n / WSZ;
    int ws  = (win & 7)  * WSZ + n % WSZ;
    int h   = hs + SHIFT; if (h >= IMG) h -= IMG;
    int x   = ws + SHIFT; if (x >= IMG) x -= IMG;
    return b * (IMG * IMG) + h * IMG + x;
}

// ------------------------- weight fp32 -> hi/lo fp16 -----------------------
__global__ void conv_kernel(const float* __restrict__ w, f16* __restrict__ hi,
                            f16* __restrict__ lo, int n) {
    for (int i = blockIdx.x * blockDim.x + threadIdx.x; i < n; i += gridDim.x * blockDim.x) {
        float v = w[i];
        f16 h = __float2half_rn(v);
        hi[i] = h;
        lo[i] = __float2half_rn(v - __half2float(h));
    }
}

// ------------------------- LayerNorm (single fp16 out) ---------------------
__global__ void ln_kernel(const float* __restrict__ in, f16* __restrict__ out,
                          const float* __restrict__ gam, const float* __restrict__ bet,
                          int M, int remap) {
    int r = blockIdx.x * (blockDim.x >> 5) + (threadIdx.x >> 5);
    if (r >= M) return;
    int lane = threadIdx.x & 31;
    int src  = remap ? win_to_orig(r) : r;
    const float* row = in + (size_t)src * DIM;

    float v[6], s = 0.f;
#pragma unroll
    for (int j = 0; j < 6; j++) { v[j] = row[lane + 32 * j]; s += v[j]; }
#pragma unroll
    for (int o = 16; o; o >>= 1) s += __shfl_xor_sync(0xFFFFFFFFu, s, o);
    float mean = s * (1.f / DIM);
    float vs = 0.f;
#pragma unroll
    for (int j = 0; j < 6; j++) { float d = v[j] - mean; vs += d * d; }
#pragma unroll
    for (int o = 16; o; o >>= 1) vs += __shfl_xor_sync(0xFFFFFFFFu, vs, o);
    float rstd = rsqrtf(vs * (1.f / DIM) + EPS);

    size_t ro = (size_t)r * DIM;
#pragma unroll
    for (int j = 0; j < 6; j++) {
        int c = lane + 32 * j;
        out[ro + c] = __float2half_rn((v[j] - mean) * rstd * gam[c] + bet[c]);
    }
}

// ------------------------- mma.sync helpers --------------------------------
__device__ __forceinline__ void ldsm4(uint32_t r[4], const f16* p) {
    uint32_t a = (uint32_t)__cvta_generic_to_shared(p);
    asm volatile("ldmatrix.sync.aligned.m8n8.x4.shared.b16 {%0,%1,%2,%3}, [%4];"
                 : "=r"(r[0]), "=r"(r[1]), "=r"(r[2]), "=r"(r[3]) : "r"(a));
}
__device__ __forceinline__ void mma16816(float c[4], const uint32_t a[4],
                                         uint32_t b0, uint32_t b1) {
    asm volatile(
        "mma.sync.aligned.m16n8k16.row.col.f32.f16.f16.f32 "
        "{%0,%1,%2,%3}, {%4,%5,%6,%7}, {%8,%9}, {%0,%1,%2,%3};"
        : "+f"(c[0]), "+f"(c[1]), "+f"(c[2]), "+f"(c[3])
        : "r"(a[0]), "r"(a[1]), "r"(a[2]), "r"(a[3]), "r"(b0), "r"(b1));
}
__device__ __forceinline__ void cp16(f16* dst, const f16* src) {
    uint32_t d = (uint32_t)__cvta_generic_to_shared(dst);
    asm volatile("cp.async.cg.shared.global [%0], [%1], 16;" :: "r"(d), "l"(src));
}
__device__ __forceinline__ void cp_commit() {
    asm volatile("cp.async.commit_group;" ::: "memory");
}
template <int N>
__device__ __forceinline__ void cp_wait() {
    asm volatile("cp.async.wait_group %0;" :: "n"(N) : "memory");
}

// ---------------------------------------------------------------------------
// GEMM: C[M,N] = A[M,K](f16) @ (Whi+Wlo)[N,K]^T + bias   (2 HMMA terms)
// BM=128, BN=64, BK=32; 256 threads (8 warps: 4 M x 2 N, 32x32 each).
// 3-stage cp.async pipeline, one __syncthreads per chunk.
// MODE 0: fp32 (qkv)   MODE 1: remap+residual (proj)
// MODE 2: GELU->f16    MODE 3: residual (fc2 -> out)
// ---------------------------------------------------------------------------
#define SKP 40                       // f16 per 32-k smem row (80 B, 16B-mult)
#define ST_A  0
#define ST_WH (128 * SKP)
#define ST_WL (192 * SKP)
#define STAGE_ELEMS (256 * SKP)      // 10240 f16 = 20480 B
#define GSMEM_BYTES (3 * STAGE_ELEMS * 2)  // 61440 B

template <int MODE>
__global__ void __launch_bounds__(256)
gemm_tc(const f16* __restrict__ A,
        const f16* __restrict__ Whi, const f16* __restrict__ Wlo,
        const float* __restrict__ bias, int N, int K,
        float* __restrict__ Cf, f16* __restrict__ Ch,
        const float* __restrict__ res) {
    extern __shared__ f16 sm[];
    const int m0 = blockIdx.y * 128, n0 = blockIdx.x * 64;
    const int tid = threadIdx.x, lane = tid & 31, w = tid >> 5;
    const int wm = w & 3, wn = w >> 2;
    const int NC = K / 32;

    auto load_stage = [&](int c) {
        f16* buf = sm + (c % 3) * STAGE_ELEMS;
        const int k0 = c * 32;
#pragma unroll
        for (int it = 0; it < 2; it++) {          // A: 512 16B chunks
            int i = tid + it * 256;
            int row = i >> 2, q = i & 3;
            cp16(buf + ST_A + row * SKP + q * 8,
                 A + (size_t)(m0 + row) * K + k0 + q * 8);
        }
        {                                          // Whi/Wlo: 256 chunks each
            int row = tid >> 2, q = tid & 3;
            size_t g = (size_t)(n0 + row) * K + k0 + q * 8;
            int so = row * SKP + q * 8;
            cp16(buf + ST_WH + so, Whi + g);
            cp16(buf + ST_WL + so, Wlo + g);
        }
        cp_commit();
    };

    float acc[2][4][4] = {};

    load_stage(0);
    load_stage(1);

    for (int c = 0; c < NC; c++) {
        if (c + 1 < NC) cp_wait<1>(); else cp_wait<0>();
        __syncthreads();
        if (c + 2 < NC) load_stage(c + 2);

        f16* buf = sm + (c % 3) * STAGE_ELEMS;
        const int lrow = lane & 15;
#pragma unroll
        for (int kk = 0; kk < 2; kk++) {
            const int lcol = kk * 16 + (lane >> 4) * 8;
            uint32_t a[2][4], wh[2][4], wl[2][4];
#pragma unroll
            for (int mi = 0; mi < 2; mi++)
                ldsm4(a[mi], buf + ST_A + (wm * 32 + mi * 16 + lrow) * SKP + lcol);
#pragma unroll
            for (int nj = 0; nj < 2; nj++) {
                const f16* pw = buf + ST_WH + (wn * 32 + nj * 16 + lrow) * SKP + lcol;
                ldsm4(wh[nj], pw);
                ldsm4(wl[nj], pw + (ST_WL - ST_WH));
            }
#pragma unroll
            for (int mi = 0; mi < 2; mi++)
#pragma unroll
                for (int nj = 0; nj < 2; nj++)
#pragma unroll
                    for (int j = 0; j < 2; j++) {
                        float* cacc = acc[mi][nj * 2 + j];
                        mma16816(cacc, a[mi], wh[nj][j], wh[nj][2 + j]);
                        mma16816(cacc, a[mi], wl[nj][j], wl[nj][2 + j]);
                    }
        }
        __syncthreads();
    }

    // ---------------- epilogue ----------------
    const int g = lane >> 2, t4 = lane & 3;
#pragma unroll
    for (int mi = 0; mi < 2; mi++) {
#pragma unroll
        for (int half = 0; half < 2; half++) {
            int r = m0 + wm * 32 + mi * 16 + g + half * 8;
            int ro = (MODE == 1) ? win_to_orig(r) : r;
#pragma unroll
            for (int ni = 0; ni < 4; ni++) {
                int cc = n0 + wn * 32 + ni * 8 + t4 * 2;
                float v0 = acc[mi][ni][half * 2 + 0] + bias[cc];
                float v1 = acc[mi][ni][half * 2 + 1] + bias[cc + 1];
                if (MODE == 0) {
                    *(float2*)&Cf[(size_t)r * N + cc] = make_float2(v0, v1);
                } else if (MODE == 1) {
                    size_t o = (size_t)ro * DIM + cc;
                    Cf[o]     = v0 + res[o];
                    Cf[o + 1] = v1 + res[o + 1];
                } else if (MODE == 2) {
                    v0 = 0.5f * v0 * (1.0f + erff(v0 * 0.70710678118654752f));
                    v1 = 0.5f * v1 * (1.0f + erff(v1 * 0.70710678118654752f));
                    *(__half2*)&Ch[(size_t)r * N + cc] = __floats2half2_rn(v0, v1);
                } else { // MODE 3
                    size_t o = (size_t)r * DIM + cc;
                    Cf[o]     = v0 + res[o];
                    Cf[o + 1] = v1 + res[o + 1];
                }
            }
        }
    }
}

// ---------------------------------------------------------------------------
// Windowed attention (fp32 math): one block per (window, head). 64 threads.
// Writes single fp16 (window layout) for the proj GEMM.
// ---------------------------------------------------------------------------
__global__ void attn_kernel(const float* __restrict__ qkv,
                            const float* __restrict__ rpb,
                            f16* __restrict__ oat) {
    __shared__ float q[NTOK][33], k[NTOK][33], v[NTOK][33];
    __shared__ float at[NTOK][51];
    __shared__ float bsh[169];

    const int w    = blockIdx.x / HEADS;
    const int head = blockIdx.x % HEADS;
    const int t    = threadIdx.x;

    const float* base = qkv + (size_t)w * NTOK * (3 * DIM) + head * 32;
    for (int idx = t; idx < NTOK * 32 * 3; idx += 64) {
        int part = idx / (NTOK * 32);
        int rem  = idx - part * NTOK * 32;
        int n = rem >> 5, d = rem & 31;
        float val = base[(size_t)n * (3 * DIM) + part * DIM + d];
        if      (part == 0) q[n][d] = val;
        else if (part == 1) k[n][d] = val;
        else                v[n][d] = val;
    }
    for (int idx = t; idx < 169; idx += 64) bsh[idx] = rpb[idx * HEADS + head];
    __syncthreads();

    if (t < NTOK) {
        const float scale = 0.17677669529663687f;
        int pin = t / WSZ, pjn = t % WSZ;
        float mx = -1e30f;
#pragma unroll 7
        for (int m = 0; m < NTOK; m++) {
            float s = 0.f;
#pragma unroll
            for (int d = 0; d < 32; d++) s = fmaf(q[t][d], k[m][d], s);
            int idx = (pin - m / WSZ + 6) * 13 + (pjn - m % WSZ + 6);
            s = s * scale + bsh[idx];
            at[t][m] = s;
            mx = fmaxf(mx, s);
        }
        float sum = 0.f;
#pragma unroll 7
        for (int m = 0; m < NTOK; m++) {
            float e = __expf(at[t][m] - mx);
            at[t][m] = e;
            sum += e;
        }
        float inv = 1.0f / sum;
        size_t orow = (size_t)(w * NTOK + t) * DIM + head * 32;
#pragma unroll
        for (int d = 0; d < 32; d++) {
            float o = 0.f;
#pragma unroll 7
            for (int m = 0; m < NTOK; m++) o = fmaf(at[t][m], v[m][d], o);
            oat[orow + d] = __float2half_rn(o * inv);
        }
    }
}

// ---------------------------------------------------------------------------
extern "C" void kernel_launch(void* const* d_in, const int* in_sizes, int n_in,
                              void* d_out, int out_size) {
    const float* x = (const float*)d_in[0];
    int base = n_in - 13;
    const float* ln1_g  = (const float*)d_in[base + 0];
    const float* ln1_b  = (const float*)d_in[base + 1];
    const float* qkv_w  = (const float*)d_in[base + 2];
    const float* qkv_b  = (const float*)d_in[base + 3];
    const float* rpb    = (const float*)d_in[base + 4];
    const float* proj_w = (const float*)d_in[base + 5];
    const float* proj_b = (const float*)d_in[base + 6];
    const float* ln2_g  = (const float*)d_in[base + 7];
    const float* ln2_b  = (const float*)d_in[base + 8];
    const float* fc1_w  = (const float*)d_in[base + 9];
    const float* fc1_b  = (const float*)d_in[base + 10];
    const float* fc2_w  = (const float*)d_in[base + 11];
    const float* fc2_b  = (const float*)d_in[base + 12];

    const int Bsz = in_sizes[0] / (IMG * IMG * DIM);
    const int M   = Bsz * IMG * IMG;

    float *qkv, *x2;
    f16 *h, *at, *hid;
    f16 *wq_hi, *wq_lo, *wp_hi, *wp_lo, *w1_hi, *w1_lo, *w2_hi, *w2_lo;
    cudaGetSymbolAddress((void**)&qkv,   g_qkv);
    cudaGetSymbolAddress((void**)&x2,    g_x2);
    cudaGetSymbolAddress((void**)&h,     g_h);
    cudaGetSymbolAddress((void**)&at,    g_at);
    cudaGetSymbolAddress((void**)&hid,   g_hid);
    cudaGetSymbolAddress((void**)&wq_hi, g_wq_hi);
    cudaGetSymbolAddress((void**)&wq_lo, g_wq_lo);
    cudaGetSymbolAddress((void**)&wp_hi, g_wp_hi);
    cudaGetSymbolAddress((void**)&wp_lo, g_wp_lo);
    cudaGetSymbolAddress((void**)&w1_hi, g_w1_hi);
    cudaGetSymbolAddress((void**)&w1_lo, g_w1_lo);
    cudaGetSymbolAddress((void**)&w2_hi, g_w2_hi);
    cudaGetSymbolAddress((void**)&w2_lo, g_w2_lo);

    cudaFuncSetAttribute(gemm_tc<0>, cudaFuncAttributeMaxDynamicSharedMemorySize, GSMEM_BYTES);
    cudaFuncSetAttribute(gemm_tc<1>, cudaFuncAttributeMaxDynamicSharedMemorySize, GSMEM_BYTES);
    cudaFuncSetAttribute(gemm_tc<2>, cudaFuncAttributeMaxDynamicSharedMemorySize, GSMEM_BYTES);
    cudaFuncSetAttribute(gemm_tc<3>, cudaFuncAttributeMaxDynamicSharedMemorySize, GSMEM_BYTES);

    const int lnGrid = (M + 7) / 8;
    const int mT = M / 128;   // 392

    conv_kernel<<<216, 256>>>(qkv_w,  wq_hi, wq_lo, 576 * DIM);
    conv_kernel<<<72,  256>>>(proj_w, wp_hi, wp_lo, DIM * DIM);
    conv_kernel<<<432, 256>>>(fc1_w,  w1_hi, w1_lo, HIDDEN * DIM);
    conv_kernel<<<432, 256>>>(fc2_w,  w2_hi, w2_lo, DIM * HIDDEN);

    // 1. LN1 fused shift + window partition -> f16
    ln_kernel<<<lnGrid, 256>>>(x, h, ln1_g, ln1_b, M, 1);
    // 2. QKV GEMM (fp32 out)
    gemm_tc<0><<<dim3(576 / 64, mT), 256, GSMEM_BYTES>>>(
        h, wq_hi, wq_lo, qkv_b, 576, DIM, qkv, nullptr, nullptr);
    // 3. attention -> f16 (window layout)
    attn_kernel<<<(M / NTOK) * HEADS, 64>>>(qkv, rpb, at);
    // 4. proj GEMM + window-reverse + residual -> x2
    gemm_tc<1><<<dim3(DIM / 64, mT), 256, GSMEM_BYTES>>>(
        at, wp_hi, wp_lo, proj_b, DIM, DIM, x2, nullptr, x);
    // 5. LN2 -> f16
    ln_kernel<<<lnGrid, 256>>>(x2, h, ln2_g, ln2_b, M, 0);
    // 6. fc1 GEMM + GELU -> f16
    gemm_tc<2><<<dim3(HIDDEN / 64, mT), 256, GSMEM_BYTES>>>(
        h, w1_hi, w1_lo, fc1_b, HIDDEN, DIM, nullptr, hid, nullptr);
    // 7. fc2 GEMM + residual -> d_out
    gemm_tc<3><<<dim3(DIM / 64, mT), 256, GSMEM_BYTES>>>(
        hid, w2_hi, w2_lo, fc2_b, DIM, HIDDEN, (float*)d_out, nullptr, x2);
}

// round 11
// speedup vs baseline: 1.8182x; 1.2853x over previous
#include <cuda_runtime.h>
#include <cuda_fp16.h>
#include <cstdint>
#include <math.h>

// ---------------------------------------------------------------------------
// SwinBlock on sm_103a — single-term fp16 HMMA GEMMs (fp32 accum),
// 3-stage cp.async pipeline, BM=128/BN=64. qkv kept in fp16.
// B=16, H=W=56, C=192, heads=6 (hd=32), WS=7, SHIFT=3, HIDDEN=1152
// ---------------------------------------------------------------------------

#define WSZ    7
#define SHIFT  3
#define HEADS  6
#define DIM    192
#define HIDDEN 1152
#define EPS    1e-5f
#define IMG    56
#define NTOK   49
#define MAXM   50176   // 16*56*56

typedef __half f16;

// ------------------------- scratch (static device) -------------------------
__device__ f16   g_qkv [(size_t)MAXM * 3 * DIM];   // fp16 qkv
__device__ float g_x2  [(size_t)MAXM * DIM];
__device__ f16   g_h   [(size_t)MAXM * DIM];       // LN out (reused LN1/LN2)
__device__ f16   g_at  [(size_t)MAXM * DIM];       // attention out (window layout)
__device__ f16   g_hid [(size_t)MAXM * HIDDEN];    // gelu(fc1)
__device__ f16   g_wq[576 * DIM];
__device__ f16   g_wp[DIM * DIM];
__device__ f16   g_w1[HIDDEN * DIM];
__device__ f16   g_w2[DIM * HIDDEN];

__device__ __forceinline__ int win_to_orig(int r) {
    int w   = r / NTOK;
    int n   = r - w * NTOK;
    int b   = w >> 6;
    int win = w & 63;
    int hs  = (win >> 3) * WSZ + n / WSZ;
    int ws  = (win & 7)  * WSZ + n % WSZ;
    int h   = hs + SHIFT; if (h >= IMG) h -= IMG;
    int x   = ws + SHIFT; if (x >= IMG) x -= IMG;
    return b * (IMG * IMG) + h * IMG + x;
}

// ------------------------- weight fp32 -> fp16 ------------------------------
__global__ void conv_kernel(const float* __restrict__ w, f16* __restrict__ o, int n) {
    int i = blockIdx.x * blockDim.x + threadIdx.x;
    if (i < n) o[i] = __float2half_rn(w[i]);
}

// ------------------------- LayerNorm (fp16 out) -----------------------------
__global__ void ln_kernel(const float* __restrict__ in, f16* __restrict__ out,
                          const float* __restrict__ gam, const float* __restrict__ bet,
                          int M, int remap) {
    int r = blockIdx.x * (blockDim.x >> 5) + (threadIdx.x >> 5);
    if (r >= M) return;
    int lane = threadIdx.x & 31;
    int src  = remap ? win_to_orig(r) : r;
    const float* row = in + (size_t)src * DIM;

    float v[6], s = 0.f;
#pragma unroll
    for (int j = 0; j < 6; j++) { v[j] = row[lane + 32 * j]; s += v[j]; }
#pragma unroll
    for (int o = 16; o; o >>= 1) s += __shfl_xor_sync(0xFFFFFFFFu, s, o);
    float mean = s * (1.f / DIM);
    float vs = 0.f;
#pragma unroll
    for (int j = 0; j < 6; j++) { float d = v[j] - mean; vs += d * d; }
#pragma unroll
    for (int o = 16; o; o >>= 1) vs += __shfl_xor_sync(0xFFFFFFFFu, vs, o);
    float rstd = rsqrtf(vs * (1.f / DIM) + EPS);

    size_t ro = (size_t)r * DIM;
#pragma unroll
    for (int j = 0; j < 6; j++) {
        int c = lane + 32 * j;
        out[ro + c] = __float2half_rn((v[j] - mean) * rstd * gam[c] + bet[c]);
    }
}

// ------------------------- mma.sync helpers --------------------------------
__device__ __forceinline__ void ldsm4(uint32_t r[4], const f16* p) {
    uint32_t a = (uint32_t)__cvta_generic_to_shared(p);
    asm volatile("ldmatrix.sync.aligned.m8n8.x4.shared.b16 {%0,%1,%2,%3}, [%4];"
                 : "=r"(r[0]), "=r"(r[1]), "=r"(r[2]), "=r"(r[3]) : "r"(a));
}
__device__ __forceinline__ void mma16816(float c[4], const uint32_t a[4],
                                         uint32_t b0, uint32_t b1) {
    asm volatile(
        "mma.sync.aligned.m16n8k16.row.col.f32.f16.f16.f32 "
        "{%0,%1,%2,%3}, {%4,%5,%6,%7}, {%8,%9}, {%0,%1,%2,%3};"
        : "+f"(c[0]), "+f"(c[1]), "+f"(c[2]), "+f"(c[3])
        : "r"(a[0]), "r"(a[1]), "r"(a[2]), "r"(a[3]), "r"(b0), "r"(b1));
}
__device__ __forceinline__ void cp16(f16* dst, const f16* src) {
    uint32_t d = (uint32_t)__cvta_generic_to_shared(dst);
    asm volatile("cp.async.cg.shared.global [%0], [%1], 16;" :: "r"(d), "l"(src));
}
__device__ __forceinline__ void cp_commit() {
    asm volatile("cp.async.commit_group;" ::: "memory");
}
template <int N>
__device__ __forceinline__ void cp_wait() {
    asm volatile("cp.async.wait_group %0;" :: "n"(N) : "memory");
}

// ---------------------------------------------------------------------------
// GEMM: C[M,N] = A[M,K](f16) @ W[N,K]^T(f16) + bias   (single HMMA term)
// BM=128, BN=64, BK=32; 256 threads (8 warps: 4 M x 2 N, 32x32 each).
// 3-stage cp.async pipeline.
// MODE 0: f16 out (qkv)  MODE 1: remap+residual fp32 (proj)
// MODE 2: GELU->f16      MODE 3: residual fp32 (fc2 -> out)
// ---------------------------------------------------------------------------
#define SKP 40                       // f16 per 32-k smem row (80 B)
#define ST_A  0
#define ST_W  (128 * SKP)
#define STAGE_ELEMS (192 * SKP)      // 7680 f16 = 15360 B
#define GSMEM_BYTES (3 * STAGE_ELEMS * 2)  // 46080 B

template <int MODE>
__global__ void __launch_bounds__(256)
gemm_tc(const f16* __restrict__ A, const f16* __restrict__ W,
        const float* __restrict__ bias, int N, int K,
        float* __restrict__ Cf, f16* __restrict__ Ch,
        const float* __restrict__ res) {
    extern __shared__ f16 sm[];
    const int m0 = blockIdx.y * 128, n0 = blockIdx.x * 64;
    const int tid = threadIdx.x, lane = tid & 31, w = tid >> 5;
    const int wm = w & 3, wn = w >> 2;
    const int NC = K / 32;

    auto load_stage = [&](int c) {
        f16* buf = sm + (c % 3) * STAGE_ELEMS;
        const int k0 = c * 32;
#pragma unroll
        for (int it = 0; it < 2; it++) {          // A: 512 16B chunks
            int i = tid + it * 256;
            int row = i >> 2, q = i & 3;
            cp16(buf + ST_A + row * SKP + q * 8,
                 A + (size_t)(m0 + row) * K + k0 + q * 8);
        }
        {                                          // W: 256 16B chunks
            int row = tid >> 2, q = tid & 3;
            cp16(buf + ST_W + row * SKP + q * 8,
                 W + (size_t)(n0 + row) * K + k0 + q * 8);
        }
        cp_commit();
    };

    float acc[2][4][4] = {};

    load_stage(0);
    load_stage(1);

    for (int c = 0; c < NC; c++) {
        if (c + 1 < NC) cp_wait<1>(); else cp_wait<0>();
        __syncthreads();
        if (c + 2 < NC) load_stage(c + 2);

        f16* buf = sm + (c % 3) * STAGE_ELEMS;
        const int lrow = lane & 15;
#pragma unroll
        for (int kk = 0; kk < 2; kk++) {
            const int lcol = kk * 16 + (lane >> 4) * 8;
            uint32_t a[2][4], wr[2][4];
#pragma unroll
            for (int mi = 0; mi < 2; mi++)
                ldsm4(a[mi], buf + ST_A + (wm * 32 + mi * 16 + lrow) * SKP + lcol);
#pragma unroll
            for (int nj = 0; nj < 2; nj++)
                ldsm4(wr[nj], buf + ST_W + (wn * 32 + nj * 16 + lrow) * SKP + lcol);
#pragma unroll
            for (int mi = 0; mi < 2; mi++)
#pragma unroll
                for (int nj = 0; nj < 2; nj++)
#pragma unroll
                    for (int j = 0; j < 2; j++)
                        mma16816(acc[mi][nj * 2 + j], a[mi], wr[nj][j], wr[nj][2 + j]);
        }
        __syncthreads();
    }

    // ---------------- epilogue ----------------
    const int g = lane >> 2, t4 = lane & 3;
#pragma unroll
    for (int mi = 0; mi < 2; mi++) {
#pragma unroll
        for (int half = 0; half < 2; half++) {
            int r = m0 + wm * 32 + mi * 16 + g + half * 8;
            int ro = (MODE == 1) ? win_to_orig(r) : r;
#pragma unroll
            for (int ni = 0; ni < 4; ni++) {
                int cc = n0 + wn * 32 + ni * 8 + t4 * 2;
                float v0 = acc[mi][ni][half * 2 + 0] + bias[cc];
                float v1 = acc[mi][ni][half * 2 + 1] + bias[cc + 1];
                if (MODE == 0) {
                    *(__half2*)&Ch[(size_t)r * N + cc] = __floats2half2_rn(v0, v1);
                } else if (MODE == 1) {
                    size_t o = (size_t)ro * DIM + cc;
                    Cf[o]     = v0 + res[o];
                    Cf[o + 1] = v1 + res[o + 1];
                } else if (MODE == 2) {
                    v0 = 0.5f * v0 * (1.0f + erff(v0 * 0.70710678118654752f));
                    v1 = 0.5f * v1 * (1.0f + erff(v1 * 0.70710678118654752f));
                    *(__half2*)&Ch[(size_t)r * N + cc] = __floats2half2_rn(v0, v1);
                } else { // MODE 3
                    size_t o = (size_t)r * DIM + cc;
                    Cf[o]     = v0 + res[o];
                    Cf[o + 1] = v1 + res[o + 1];
                }
            }
        }
    }
}

// ---------------------------------------------------------------------------
// Windowed attention: one block per (window, head). 64 threads.
// Reads fp16 qkv, computes in fp32, writes fp16 (window layout).
// ---------------------------------------------------------------------------
__global__ void attn_kernel(const f16* __restrict__ qkv,
                            const float* __restrict__ rpb,
                            f16* __restrict__ oat) {
    __shared__ float q[NTOK][33], k[NTOK][33], v[NTOK][33];
    __shared__ float at[NTOK][51];
    __shared__ float bsh[169];

    const int w    = blockIdx.x / HEADS;
    const int head = blockIdx.x % HEADS;
    const int t    = threadIdx.x;

    const f16* base = qkv + (size_t)w * NTOK * (3 * DIM) + head * 32;
    for (int idx = t; idx < NTOK * 32 * 3; idx += 64) {
        int part = idx / (NTOK * 32);
        int rem  = idx - part * NTOK * 32;
        int n = rem >> 5, d = rem & 31;
        float val = __half2float(base[(size_t)n * (3 * DIM) + part * DIM + d]);
        if      (part == 0) q[n][d] = val;
        else if (part == 1) k[n][d] = val;
        else                v[n][d] = val;
    }
    for (int idx = t; idx < 169; idx += 64) bsh[idx] = rpb[idx * HEADS + head];
    __syncthreads();

    if (t < NTOK) {
        const float scale = 0.17677669529663687f;
        int pin = t / WSZ, pjn = t % WSZ;
        float mx = -1e30f;
#pragma unroll 7
        for (int m = 0; m < NTOK; m++) {
            float s = 0.f;
#pragma unroll
            for (int d = 0; d < 32; d++) s = fmaf(q[t][d], k[m][d], s);
            int idx = (pin - m / WSZ + 6) * 13 + (pjn - m % WSZ + 6);
            s = s * scale + bsh[idx];
            at[t][m] = s;
            mx = fmaxf(mx, s);
        }
        float sum = 0.f;
#pragma unroll 7
        for (int m = 0; m < NTOK; m++) {
            float e = __expf(at[t][m] - mx);
            at[t][m] = e;
            sum += e;
        }
        float inv = 1.0f / sum;
        size_t orow = (size_t)(w * NTOK + t) * DIM + head * 32;
#pragma unroll
        for (int d = 0; d < 32; d++) {
            float o = 0.f;
#pragma unroll 7
            for (int m = 0; m < NTOK; m++) o = fmaf(at[t][m], v[m][d], o);
            oat[orow + d] = __float2half_rn(o * inv);
        }
    }
}

// ---------------------------------------------------------------------------
extern "C" void kernel_launch(void* const* d_in, const int* in_sizes, int n_in,
                              void* d_out, int out_size) {
    const float* x = (const float*)d_in[0];
    int base = n_in - 13;
    const float* ln1_g  = (const float*)d_in[base + 0];
    const float* ln1_b  = (const float*)d_in[base + 1];
    const float* qkv_w  = (const float*)d_in[base + 2];
    const float* qkv_b  = (const float*)d_in[base + 3];
    const float* rpb    = (const float*)d_in[base + 4];
    const float* proj_w = (const float*)d_in[base + 5];
    const float* proj_b = (const float*)d_in[base + 6];
    const float* ln2_g  = (const float*)d_in[base + 7];
    const float* ln2_b  = (const float*)d_in[base + 8];
    const float* fc1_w  = (const float*)d_in[base + 9];
    const float* fc1_b  = (const float*)d_in[base + 10];
    const float* fc2_w  = (const float*)d_in[base + 11];
    const float* fc2_b  = (const float*)d_in[base + 12];

    const int Bsz = in_sizes[0] / (IMG * IMG * DIM);
    const int M   = Bsz * IMG * IMG;

    float *x2;
    f16 *qkv, *h, *at, *hid, *wq, *wp, *w1, *w2;
    cudaGetSymbolAddress((void**)&qkv, g_qkv);
    cudaGetSymbolAddress((void**)&x2,  g_x2);
    cudaGetSymbolAddress((void**)&h,   g_h);
    cudaGetSymbolAddress((void**)&at,  g_at);
    cudaGetSymbolAddress((void**)&hid, g_hid);
    cudaGetSymbolAddress((void**)&wq,  g_wq);
    cudaGetSymbolAddress((void**)&wp,  g_wp);
    cudaGetSymbolAddress((void**)&w1,  g_w1);
    cudaGetSymbolAddress((void**)&w2,  g_w2);

    cudaFuncSetAttribute(gemm_tc<0>, cudaFuncAttributeMaxDynamicSharedMemorySize, GSMEM_BYTES);
    cudaFuncSetAttribute(gemm_tc<1>, cudaFuncAttributeMaxDynamicSharedMemorySize, GSMEM_BYTES);
    cudaFuncSetAttribute(gemm_tc<2>, cudaFuncAttributeMaxDynamicSharedMemorySize, GSMEM_BYTES);
    cudaFuncSetAttribute(gemm_tc<3>, cudaFuncAttributeMaxDynamicSharedMemorySize, GSMEM_BYTES);

    const int lnGrid = (M + 7) / 8;
    const int mT = M / 128;   // 392

    conv_kernel<<<(576 * DIM + 255) / 256, 256>>>(qkv_w, wq, 576 * DIM);
    conv_kernel<<<(DIM * DIM + 255) / 256, 256>>>(proj_w, wp, DIM * DIM);
    conv_kernel<<<(HIDDEN * DIM + 255) / 256, 256>>>(fc1_w, w1, HIDDEN * DIM);
    conv_kernel<<<(DIM * HIDDEN + 255) / 256, 256>>>(fc2_w, w2, DIM * HIDDEN);

    // 1. LN1 fused shift + window partition -> f16
    ln_kernel<<<lnGrid, 256>>>(x, h, ln1_g, ln1_b, M, 1);
    // 2. QKV GEMM -> f16
    gemm_tc<0><<<dim3(576 / 64, mT), 256, GSMEM_BYTES>>>(
        h, wq, qkv_b, 576, DIM, nullptr, qkv, nullptr);
    // 3. attention -> f16 (window layout)
    attn_kernel<<<(M / NTOK) * HEADS, 64>>>(qkv, rpb, at);
    // 4. proj GEMM + window-reverse + residual -> x2 (fp32)
    gemm_tc<1><<<dim3(DIM / 64, mT), 256, GSMEM_BYTES>>>(
        at, wp, proj_b, DIM, DIM, x2, nullptr, x);
    // 5. LN2 -> f16
    ln_kernel<<<lnGrid, 256>>>(x2, h, ln2_g, ln2_b, M, 0);
    // 6. fc1 GEMM + GELU -> f16
    gemm_tc<2><<<dim3(HIDDEN / 64, mT), 256, GSMEM_BYTES>>>(
        h, w1, fc1_b, HIDDEN, DIM, nullptr, hid, nullptr);
    // 7. fc2 GEMM + residual -> d_out (fp32)
    gemm_tc<3><<<dim3(DIM / 64, mT), 256, GSMEM_BYTES>>>(
        hid, w2, fc2_b, DIM, HIDDEN, (float*)d_out, nullptr, x2);
}

// round 13
// speedup vs baseline: 3.0888x; 1.6988x over previous
#include <cuda_runtime.h>
#include <cuda_fp16.h>
#include <cstdint>
#include <math.h>

// ---------------------------------------------------------------------------
// SwinBlock on sm_103a — fp16 HMMA GEMMs + HMMA windowed attention.
// B=16, H=W=56, C=192, heads=6 (hd=32), WS=7, SHIFT=3, HIDDEN=1152
// ---------------------------------------------------------------------------

#define WSZ    7
#define SHIFT  3
#define HEADS  6
#define DIM    192
#define HIDDEN 1152
#define EPS    1e-5f
#define IMG    56
#define NTOK   49
#define MAXM   50176   // 16*56*56

typedef __half f16;

// ------------------------- scratch (static device) -------------------------
__device__ f16   g_qkv [(size_t)MAXM * 3 * DIM];
__device__ float g_x2  [(size_t)MAXM * DIM];
__device__ f16   g_h   [(size_t)MAXM * DIM];
__device__ f16   g_at  [(size_t)MAXM * DIM];
__device__ f16   g_hid [(size_t)MAXM * HIDDEN];
__device__ f16   g_wq[576 * DIM];
__device__ f16   g_wp[DIM * DIM];
__device__ f16   g_w1[HIDDEN * DIM];
__device__ f16   g_w2[DIM * HIDDEN];

__device__ __forceinline__ int win_to_orig(int r) {
    int w   = r / NTOK;
    int n   = r - w * NTOK;
    int b   = w >> 6;
    int win = w & 63;
    int hs  = (win >> 3) * WSZ + n / WSZ;
    int ws  = (win & 7)  * WSZ + n % WSZ;
    int h   = hs + SHIFT; if (h >= IMG) h -= IMG;
    int x   = ws + SHIFT; if (x >= IMG) x -= IMG;
    return b * (IMG * IMG) + h * IMG + x;
}

// ------------------------- weight fp32 -> fp16 ------------------------------
__global__ void conv_kernel(const float* __restrict__ w, f16* __restrict__ o, int n) {
    int i = blockIdx.x * blockDim.x + threadIdx.x;
    if (i < n) o[i] = __float2half_rn(w[i]);
}

// ------------------------- LayerNorm (fp16 out) -----------------------------
__global__ void ln_kernel(const float* __restrict__ in, f16* __restrict__ out,
                          const float* __restrict__ gam, const float* __restrict__ bet,
                          int M, int remap) {
    int r = blockIdx.x * (blockDim.x >> 5) + (threadIdx.x >> 5);
    if (r >= M) return;
    int lane = threadIdx.x & 31;
    int src  = remap ? win_to_orig(r) : r;
    const float* row = in + (size_t)src * DIM;

    float v[6], s = 0.f;
#pragma unroll
    for (int j = 0; j < 6; j++) { v[j] = row[lane + 32 * j]; s += v[j]; }
#pragma unroll
    for (int o = 16; o; o >>= 1) s += __shfl_xor_sync(0xFFFFFFFFu, s, o);
    float mean = s * (1.f / DIM);
    float vs = 0.f;
#pragma unroll
    for (int j = 0; j < 6; j++) { float d = v[j] - mean; vs += d * d; }
#pragma unroll
    for (int o = 16; o; o >>= 1) vs += __shfl_xor_sync(0xFFFFFFFFu, vs, o);
    float rstd = rsqrtf(vs * (1.f / DIM) + EPS);

    size_t ro = (size_t)r * DIM;
#pragma unroll
    for (int j = 0; j < 6; j++) {
        int c = lane + 32 * j;
        out[ro + c] = __float2half_rn((v[j] - mean) * rstd * gam[c] + bet[c]);
    }
}

// ------------------------- mma.sync helpers --------------------------------
__device__ __forceinline__ void ldsm4(uint32_t r[4], const f16* p) {
    uint32_t a = (uint32_t)__cvta_generic_to_shared(p);
    asm volatile("ldmatrix.sync.aligned.m8n8.x4.shared.b16 {%0,%1,%2,%3}, [%4];"
                 : "=r"(r[0]), "=r"(r[1]), "=r"(r[2]), "=r"(r[3]) : "r"(a));
}
__device__ __forceinline__ void mma16816(float c[4], const uint32_t a[4],
                                         uint32_t b0, uint32_t b1) {
    asm volatile(
        "mma.sync.aligned.m16n8k16.row.col.f32.f16.f16.f32 "
        "{%0,%1,%2,%3}, {%4,%5,%6,%7}, {%8,%9}, {%0,%1,%2,%3};"
        : "+f"(c[0]), "+f"(c[1]), "+f"(c[2]), "+f"(c[3])
        : "r"(a[0]), "r"(a[1]), "r"(a[2]), "r"(a[3]), "r"(b0), "r"(b1));
}
__device__ __forceinline__ void cp16(f16* dst, const f16* src) {
    uint32_t d = (uint32_t)__cvta_generic_to_shared(dst);
    asm volatile("cp.async.cg.shared.global [%0], [%1], 16;" :: "r"(d), "l"(src));
}
__device__ __forceinline__ void cp_commit() {
    asm volatile("cp.async.commit_group;" ::: "memory");
}
template <int N>
__device__ __forceinline__ void cp_wait() {
    asm volatile("cp.async.wait_group %0;" :: "n"(N) : "memory");
}
__device__ __forceinline__ uint32_t h2u(float a, float b) {
    __half2 t = __floats2half2_rn(a, b);
    return *(uint32_t*)&t;
}

// ---------------------------------------------------------------------------
// GEMM: C = A(f16) @ W^T(f16) + bias, BM128/BN64/BK32, 3-stage cp.async.
// MODE 0 f16, 1 remap+res fp32, 2 GELU f16, 3 res fp32.
// ---------------------------------------------------------------------------
#define SKP 40
#define ST_A  0
#define ST_W  (128 * SKP)
#define STAGE_ELEMS (192 * SKP)
#define GSMEM_BYTES (3 * STAGE_ELEMS * 2)

template <int MODE>
__global__ void __launch_bounds__(256)
gemm_tc(const f16* __restrict__ A, const f16* __restrict__ W,
        const float* __restrict__ bias, int N, int K,
        float* __restrict__ Cf, f16* __restrict__ Ch,
        const float* __restrict__ res) {
    extern __shared__ f16 sm[];
    const int m0 = blockIdx.y * 128, n0 = blockIdx.x * 64;
    const int tid = threadIdx.x, lane = tid & 31, w = tid >> 5;
    const int wm = w & 3, wn = w >> 2;
    const int NC = K / 32;

    auto load_stage = [&](int c) {
        f16* buf = sm + (c % 3) * STAGE_ELEMS;
        const int k0 = c * 32;
#pragma unroll
        for (int it = 0; it < 2; it++) {
            int i = tid + it * 256;
            int row = i >> 2, q = i & 3;
            cp16(buf + ST_A + row * SKP + q * 8,
                 A + (size_t)(m0 + row) * K + k0 + q * 8);
        }
        {
            int row = tid >> 2, q = tid & 3;
            cp16(buf + ST_W + row * SKP + q * 8,
                 W + (size_t)(n0 + row) * K + k0 + q * 8);
        }
        cp_commit();
    };

    float acc[2][4][4] = {};

    load_stage(0);
    load_stage(1);

    for (int c = 0; c < NC; c++) {
        if (c + 1 < NC) cp_wait<1>(); else cp_wait<0>();
        __syncthreads();
        if (c + 2 < NC) load_stage(c + 2);

        f16* buf = sm + (c % 3) * STAGE_ELEMS;
        const int lrow = lane & 15;
#pragma unroll
        for (int kk = 0; kk < 2; kk++) {
            const int lcol = kk * 16 + (lane >> 4) * 8;
            uint32_t a[2][4], wr[2][4];
#pragma unroll
            for (int mi = 0; mi < 2; mi++)
                ldsm4(a[mi], buf + ST_A + (wm * 32 + mi * 16 + lrow) * SKP + lcol);
#pragma unroll
            for (int nj = 0; nj < 2; nj++)
                ldsm4(wr[nj], buf + ST_W + (wn * 32 + nj * 16 + lrow) * SKP + lcol);
#pragma unroll
            for (int mi = 0; mi < 2; mi++)
#pragma unroll
                for (int nj = 0; nj < 2; nj++)
#pragma unroll
                    for (int j = 0; j < 2; j++)
                        mma16816(acc[mi][nj * 2 + j], a[mi], wr[nj][j], wr[nj][2 + j]);
        }
        __syncthreads();
    }

    const int g = lane >> 2, t4 = lane & 3;
#pragma unroll
    for (int mi = 0; mi < 2; mi++) {
#pragma unroll
        for (int half = 0; half < 2; half++) {
            int r = m0 + wm * 32 + mi * 16 + g + half * 8;
            int ro = (MODE == 1) ? win_to_orig(r) : r;
#pragma unroll
            for (int ni = 0; ni < 4; ni++) {
                int cc = n0 + wn * 32 + ni * 8 + t4 * 2;
                float v0 = acc[mi][ni][half * 2 + 0] + bias[cc];
                float v1 = acc[mi][ni][half * 2 + 1] + bias[cc + 1];
                if (MODE == 0) {
                    *(__half2*)&Ch[(size_t)r * N + cc] = __floats2half2_rn(v0, v1);
                } else if (MODE == 1) {
                    size_t o = (size_t)ro * DIM + cc;
                    Cf[o]     = v0 + res[o];
                    Cf[o + 1] = v1 + res[o + 1];
                } else if (MODE == 2) {
                    v0 = 0.5f * v0 * (1.0f + erff(v0 * 0.70710678118654752f));
                    v1 = 0.5f * v1 * (1.0f + erff(v1 * 0.70710678118654752f));
                    *(__half2*)&Ch[(size_t)r * N + cc] = __floats2half2_rn(v0, v1);
                } else {
                    size_t o = (size_t)r * DIM + cc;
                    Cf[o]     = v0 + res[o];
                    Cf[o + 1] = v1 + res[o + 1];
                }
            }
        }
    }
}

// ---------------------------------------------------------------------------
// HMMA windowed attention.
// 4 (window,head) pairs per 256-thread block; 2 warps per pair (32 rows each).
// QK^T: m64n64k32; softmax on fragments; AV: m64n32k64 vs V^T [d][token].
// ---------------------------------------------------------------------------
#define AQ_ELEMS (64 * 40)          // q halves
#define AK_ELEMS (64 * 40)
#define AV_ELEMS (32 * 72)          // vT halves
#define PAIR_HALVES (AQ_ELEMS + AK_ELEMS + AV_ELEMS)   // 7424
#define PAIR_BYTES  (PAIR_HALVES * 2 + 704)            // + bias(169f)+pad = 15552
#define ATT_SMEM    (4 * PAIR_BYTES)                   // 62208

__global__ void __launch_bounds__(256)
attn_mma(const f16* __restrict__ qkv, const float* __restrict__ rpb,
         f16* __restrict__ oat) {
    extern __shared__ char asmem[];
    const int tid  = threadIdx.x;
    const int warp = tid >> 5, lane = tid & 31;
    const int p    = warp >> 1, wp = warp & 1;
    const int pair = blockIdx.x * 4 + p;
    const int w    = pair / HEADS, h = pair % HEADS;

    f16*   q   = (f16*)(asmem + p * PAIR_BYTES);
    f16*   k   = q + AQ_ELEMS;
    f16*   vT  = k + AK_ELEMS;
    float* bsh = (float*)(vT + AV_ELEMS);
    const int t64 = tid & 63;

    // zero all pair smem (pads must be 0)
    for (int i = t64; i < PAIR_HALVES / 8; i += 64)
        ((uint4*)q)[i] = make_uint4(0, 0, 0, 0);
    __syncthreads();

    // fill q, k, vT (49 tokens x 32 d), bias table
    const f16* qg = qkv + (size_t)(w * NTOK) * (3 * DIM) + h * 32;
    for (int i = t64; i < NTOK * 16; i += 64) {
        int t = i >> 4, d2 = (i & 15) * 2;
        const f16* src = qg + (size_t)t * (3 * DIM) + d2;
        *(__half2*)(q + t * 40 + d2) = *(const __half2*)(src);
        *(__half2*)(k + t * 40 + d2) = *(const __half2*)(src + DIM);
        __half2 vv = *(const __half2*)(src + 2 * DIM);
        vT[d2 * 72 + t]       = __low2half(vv);
        vT[(d2 + 1) * 72 + t] = __high2half(vv);
    }
    for (int i = t64; i < 169; i += 64) bsh[i] = rpb[i * HEADS + h];
    __syncthreads();

    const int lrow = lane & 15;
    const int lhi8 = (lane >> 4) * 8;
    const int g = lane >> 2, t4 = lane & 3;

    // ---- QK^T ----
    float acc[2][8][4] = {};
#pragma unroll
    for (int kk = 0; kk < 2; kk++) {
        const int lcol = kk * 16 + lhi8;
        uint32_t a[2][4];
#pragma unroll
        for (int mi = 0; mi < 2; mi++)
            ldsm4(a[mi], q + (wp * 32 + mi * 16 + lrow) * 40 + lcol);
#pragma unroll
        for (int nj4 = 0; nj4 < 4; nj4++) {
            uint32_t wr[4];
            ldsm4(wr, k + (nj4 * 16 + lrow) * 40 + lcol);
#pragma unroll
            for (int mi = 0; mi < 2; mi++)
#pragma unroll
                for (int j = 0; j < 2; j++)
                    mma16816(acc[mi][nj4 * 2 + j], a[mi], wr[j], wr[2 + j]);
        }
    }

    // ---- softmax on fragments ----
    const float scale = 0.17677669529663687f;
    float mx[2][2], sums[2][2];
    int rq7[2][2], rm7[2][2], rr[2][2];
#pragma unroll
    for (int mi = 0; mi < 2; mi++)
#pragma unroll
        for (int hf = 0; hf < 2; hf++) {
            int r = wp * 32 + mi * 16 + g + 8 * hf;
            rr[mi][hf] = r;
            int rd = (r * 37) >> 8;
            rq7[mi][hf] = rd; rm7[mi][hf] = r - 7 * rd;
            mx[mi][hf] = -1e30f; sums[mi][hf] = 0.f;
        }
#pragma unroll
    for (int mi = 0; mi < 2; mi++)
#pragma unroll
        for (int nj = 0; nj < 8; nj++)
#pragma unroll
            for (int cj = 0; cj < 4; cj++) {
                int hf = cj >> 1;
                int c  = nj * 8 + 2 * t4 + (cj & 1);
                float s;
                // guard BOTH row and col: rows >= 49 must not index bsh
                if (c < NTOK && rr[mi][hf] < NTOK) {
                    int cd = (c * 37) >> 8, cm = c - 7 * cd;
                    int idx = (rq7[mi][hf] - cd + 6) * 13 + (rm7[mi][hf] - cm + 6);
                    s = acc[mi][nj][cj] * scale + bsh[idx];
                } else s = -1e30f;
                acc[mi][nj][cj] = s;
                mx[mi][hf] = fmaxf(mx[mi][hf], s);
            }
#pragma unroll
    for (int mi = 0; mi < 2; mi++)
#pragma unroll
        for (int hf = 0; hf < 2; hf++) {
            float m = mx[mi][hf];
            m = fmaxf(m, __shfl_xor_sync(0xFFFFFFFFu, m, 1));
            m = fmaxf(m, __shfl_xor_sync(0xFFFFFFFFu, m, 2));
            mx[mi][hf] = m;
        }
#pragma unroll
    for (int mi = 0; mi < 2; mi++)
#pragma unroll
        for (int nj = 0; nj < 8; nj++)
#pragma unroll
            for (int cj = 0; cj < 4; cj++) {
                int hf = cj >> 1;
                float e = __expf(acc[mi][nj][cj] - mx[mi][hf]);
                acc[mi][nj][cj] = e;
                sums[mi][hf] += e;
            }
#pragma unroll
    for (int mi = 0; mi < 2; mi++)
#pragma unroll
        for (int hf = 0; hf < 2; hf++) {
            float s = sums[mi][hf];
            s += __shfl_xor_sync(0xFFFFFFFFu, s, 1);
            s += __shfl_xor_sync(0xFFFFFFFFu, s, 2);
            sums[mi][hf] = s;
        }

    // ---- pack P into A fragments (C-frag -> A-frag identity) ----
    uint32_t pa[2][4][4];
#pragma unroll
    for (int mi = 0; mi < 2; mi++)
#pragma unroll
        for (int kt = 0; kt < 4; kt++) {
            pa[mi][kt][0] = h2u(acc[mi][2 * kt][0],     acc[mi][2 * kt][1]);
            pa[mi][kt][1] = h2u(acc[mi][2 * kt][2],     acc[mi][2 * kt][3]);
            pa[mi][kt][2] = h2u(acc[mi][2 * kt + 1][0], acc[mi][2 * kt + 1][1]);
            pa[mi][kt][3] = h2u(acc[mi][2 * kt + 1][2], acc[mi][2 * kt + 1][3]);
        }

    // ---- AV ----
    float o[2][4][4] = {};
#pragma unroll
    for (int kt = 0; kt < 4; kt++) {
        const int kc = kt * 16 + lhi8;
#pragma unroll
        for (int nv = 0; nv < 2; nv++) {
            uint32_t wr[4];
            ldsm4(wr, vT + (nv * 16 + lrow) * 72 + kc);
#pragma unroll
            for (int mi = 0; mi < 2; mi++)
#pragma unroll
                for (int j = 0; j < 2; j++)
                    mma16816(o[mi][nv * 2 + j], pa[mi][kt], wr[j], wr[2 + j]);
        }
    }

    // ---- normalize + store (rows < 49) ----
#pragma unroll
    for (int mi = 0; mi < 2; mi++)
#pragma unroll
        for (int hf = 0; hf < 2; hf++) {
            int r = rr[mi][hf];
            if (r < NTOK) {
                float inv = 1.f / sums[mi][hf];
                f16* orow = oat + (size_t)(w * NTOK + r) * DIM + h * 32;
#pragma unroll
                for (int nd = 0; nd < 4; nd++) {
                    int d0 = nd * 8 + 2 * t4;
                    *(__half2*)(orow + d0) = __floats2half2_rn(
                        o[mi][nd][hf * 2 + 0] * inv, o[mi][nd][hf * 2 + 1] * inv);
                }
            }
        }
}

// ---------------------------------------------------------------------------
extern "C" void kernel_launch(void* const* d_in, const int* in_sizes, int n_in,
                              void* d_out, int out_size) {
    const float* x = (const float*)d_in[0];
    int base = n_in - 13;
    const float* ln1_g  = (const float*)d_in[base + 0];
    const float* ln1_b  = (const float*)d_in[base + 1];
    const float* qkv_w  = (const float*)d_in[base + 2];
    const float* qkv_b  = (const float*)d_in[base + 3];
    const float* rpb    = (const float*)d_in[base + 4];
    const float* proj_w = (const float*)d_in[base + 5];
    const float* proj_b = (const float*)d_in[base + 6];
    const float* ln2_g  = (const float*)d_in[base + 7];
    const float* ln2_b  = (const float*)d_in[base + 8];
    const float* fc1_w  = (const float*)d_in[base + 9];
    const float* fc1_b  = (const float*)d_in[base + 10];
    const float* fc2_w  = (const float*)d_in[base + 11];
    const float* fc2_b  = (const float*)d_in[base + 12];

    const int Bsz = in_sizes[0] / (IMG * IMG * DIM);
    const int M   = Bsz * IMG * IMG;

    float *x2;
    f16 *qkv, *h, *at, *hid, *wq, *wp, *w1, *w2;
    cudaGetSymbolAddress((void**)&qkv, g_qkv);
    cudaGetSymbolAddress((void**)&x2,  g_x2);
    cudaGetSymbolAddress((void**)&h,   g_h);
    cudaGetSymbolAddress((void**)&at,  g_at);
    cudaGetSymbolAddress((void**)&hid, g_hid);
    cudaGetSymbolAddress((void**)&wq,  g_wq);
    cudaGetSymbolAddress((void**)&wp,  g_wp);
    cudaGetSymbolAddress((void**)&w1,  g_w1);
    cudaGetSymbolAddress((void**)&w2,  g_w2);

    cudaFuncSetAttribute(gemm_tc<0>, cudaFuncAttributeMaxDynamicSharedMemorySize, GSMEM_BYTES);
    cudaFuncSetAttribute(gemm_tc<1>, cudaFuncAttributeMaxDynamicSharedMemorySize, GSMEM_BYTES);
    cudaFuncSetAttribute(gemm_tc<2>, cudaFuncAttributeMaxDynamicSharedMemorySize, GSMEM_BYTES);
    cudaFuncSetAttribute(gemm_tc<3>, cudaFuncAttributeMaxDynamicSharedMemorySize, GSMEM_BYTES);
    cudaFuncSetAttribute(attn_mma,   cudaFuncAttributeMaxDynamicSharedMemorySize, ATT_SMEM);

    const int lnGrid = (M + 7) / 8;
    const int mT = M / 128;   // 392
    const int nPairs = (M / NTOK) * HEADS;   // 6144

    conv_kernel<<<(576 * DIM + 255) / 256, 256>>>(qkv_w, wq, 576 * DIM);
    conv_kernel<<<(DIM * DIM + 255) / 256, 256>>>(proj_w, wp, DIM * DIM);
    conv_kernel<<<(HIDDEN * DIM + 255) / 256, 256>>>(fc1_w, w1, HIDDEN * DIM);
    conv_kernel<<<(DIM * HIDDEN + 255) / 256, 256>>>(fc2_w, w2, DIM * HIDDEN);

    // 1. LN1 fused shift + window partition -> f16
    ln_kernel<<<lnGrid, 256>>>(x, h, ln1_g, ln1_b, M, 1);
    // 2. QKV GEMM -> f16
    gemm_tc<0><<<dim3(576 / 64, mT), 256, GSMEM_BYTES>>>(
        h, wq, qkv_b, 576, DIM, nullptr, qkv, nullptr);
    // 3. HMMA attention -> f16 (window layout)
    attn_mma<<<nPairs / 4, 256, ATT_SMEM>>>(qkv, rpb, at);
    // 4. proj GEMM + window-reverse + residual -> x2 (fp32)
    gemm_tc<1><<<dim3(DIM / 64, mT), 256, GSMEM_BYTES>>>(
        at, wp, proj_b, DIM, DIM, x2, nullptr, x);
    // 5. LN2 -> f16
    ln_kernel<<<lnGrid, 256>>>(x2, h, ln2_g, ln2_b, M, 0);
    // 6. fc1 GEMM + GELU -> f16
    gemm_tc<2><<<dim3(HIDDEN / 64, mT), 256, GSMEM_BYTES>>>(
        h, w1, fc1_b, HIDDEN, DIM, nullptr, hid, nullptr);
    // 7. fc2 GEMM + residual -> d_out (fp32)
    gemm_tc<3><<<dim3(DIM / 64, mT), 256, GSMEM_BYTES>>>(
        hid, w2, fc2_b, DIM, HIDDEN, (float*)d_out, nullptr, x2);
}